// round 17
// baseline (speedup 1.0000x reference)
#include <cuda_runtime.h>
#include <cuda_fp16.h>
#include <math.h>

// Problem dims
#define Bsz 256
#define Tlen 64
#define EMB 256
#define UNITS 512
#define G4 2048          // 4*UNITS
#define N2 4096          // fwd+bwd gate width
#define ROWS (Bsz*Tlen)  // 16384
#define VOCAB 10000

// ---------------- scratch (device globals; no allocation allowed) ----------
__device__ __half g_pooled16[Bsz * 2048];
__device__ __half g_xw16[(size_t)ROWS * N2];      // 128 MiB fp16 gate preacts
__device__ __half g_seq1h[(size_t)ROWS * 1024];   // lstm1 output (fp16)
__device__ __half g_hh0[2 * Bsz * UNITS];         // h ping (fp16)
__device__ __half g_hh1[2 * Bsz * UNITS];         // h pong (fp16)
__device__ __half g_emb16[VOCAB * EMB];
__device__ __half g_l1Wi16[(size_t)N2 * EMB];     // [4096][256]  (transposed)
__device__ __half g_l2Wi16[(size_t)N2 * 1024];    // [4096][1024] (transposed)
__device__ __half g_W1T[(size_t)1024 * 3072];     // [1024][3072] (transposed)
__device__ __half g_W2T[(size_t)512 * 1024];      // [512][1024]  (transposed)
__device__ float  g_bias1[N2];
__device__ float  g_bias2[N2];
__device__ __half g_x1h[Bsz * 1024];
__device__ __half g_x2h[Bsz * 512];
__device__ float  g_part[4 * Bsz * 1024];         // split-K partials (4 MB)

// group barrier state: 4 groups (bm x dir) of 32 blocks, separate cache lines
__device__ unsigned g_gcount[4][32];
__device__ volatile unsigned g_ggen[4][32];

__device__ __forceinline__ void group_barrier(int gid) {
    __threadfence();
    __syncthreads();
    if (threadIdx.x == 0) {
        unsigned gen = g_ggen[gid][0];
        if (atomicAdd(&g_gcount[gid][0], 1u) == 31u) {
            atomicExch(&g_gcount[gid][0], 0u);
            __threadfence();
            g_ggen[gid][0] = gen + 1;
        } else {
            while (g_ggen[gid][0] == gen) { }
        }
    }
    __syncthreads();
}

// ================= MMA / async / math helpers ==============================
__device__ __forceinline__ void mma_f16(float* d, const unsigned* a, const unsigned* b) {
    asm volatile(
        "mma.sync.aligned.m16n8k16.row.col.f32.f16.f16.f32 "
        "{%0,%1,%2,%3},{%4,%5,%6,%7},{%8,%9},{%0,%1,%2,%3};\n"
        : "+f"(d[0]), "+f"(d[1]), "+f"(d[2]), "+f"(d[3])
        : "r"(a[0]), "r"(a[1]), "r"(a[2]), "r"(a[3]), "r"(b[0]), "r"(b[1]));
}

__device__ __forceinline__ void ldsm_x4(unsigned* r, unsigned addr) {
    asm volatile("ldmatrix.sync.aligned.m8n8.x4.shared.b16 {%0,%1,%2,%3}, [%4];"
                 : "=r"(r[0]), "=r"(r[1]), "=r"(r[2]), "=r"(r[3]) : "r"(addr));
}

__device__ __forceinline__ void cp16(void* smem_dst, const void* gsrc) {
    unsigned s = (unsigned)__cvta_generic_to_shared(smem_dst);
    asm volatile("cp.async.cg.shared.global [%0], [%1], 16;\n" :: "r"(s), "l"(gsrc));
}

__device__ __forceinline__ float tanh_fast(float x) {
    float r;
    asm("tanh.approx.f32 %0, %1;" : "=f"(r) : "f"(x));
    return r;
}
__device__ __forceinline__ float sig_fast(float x) {
    return fmaf(tanh_fast(0.5f * x), 0.5f, 0.5f);
}

// feats view: cols [0,2048) = pooled16, [2048,3072) = h (dir-split)
__device__ __forceinline__ const __half* feats_ptr(const __half* pooled16,
                                                   const __half* hfin,
                                                   int row, int c) {
    if (c < 2048) return pooled16 + (size_t)row * 2048 + c;
    int c2 = c - 2048;
    return hfin + (c2 >> 9) * 131072 + (size_t)row * 512 + (c2 & 511);
}

// ================= fused prologue: conversions + pooled mean (fp16) ========
#define PREP_BLOCKS 12034

__global__ void prep_kernel(const float* __restrict__ emb,
                            const float* __restrict__ l1fWi, const float* __restrict__ l1bWi,
                            const float* __restrict__ l2fWi, const float* __restrict__ l2bWi,
                            const float* __restrict__ W1, const float* __restrict__ W2,
                            const float* __restrict__ l1fb, const float* __restrict__ l1bb,
                            const float* __restrict__ l2fb, const float* __restrict__ l2bb,
                            const float* __restrict__ enc,
                            __half* __restrict__ emb16, __half* __restrict__ l1Wi16,
                            __half* __restrict__ l2Wi16, __half* __restrict__ W1T,
                            __half* __restrict__ W2T,
                            float* __restrict__ bias1, float* __restrict__ bias2,
                            __half* __restrict__ pooled16) {
    int bid = blockIdx.x, tid = threadIdx.x;
    if (bid < 1250) {
        int i0 = bid * 2048 + tid;
#pragma unroll
        for (int s = 0; s < 8; s++) {
            int i = i0 + s * 256;
            if (i < VOCAB * EMB) emb16[i] = __float2half(emb[i]);
        }
        return;
    }
    if (bid >= 9986) {
        int idx = (bid - 9986) * 256 + tid;
        int b = idx >> 11;
        int c = idx & 2047;
        const float* p = enc + (size_t)b * 100 * 2048 + c;
        float s = 0.f;
#pragma unroll 4
        for (int q = 0; q < 100; q++) s += p[q * 2048];
        pooled16[idx] = __float2half(s * 0.01f);
        return;
    }
    if (bid >= 9954) {
        int i = (bid - 9954) * 256 + tid;
        if (i < 4096) bias1[i] = (i < 2048) ? l1fb[i] : l1bb[i - 2048];
        else { int k = i - 4096; bias2[k] = (k < 2048) ? l2fb[k] : l2bb[k - 2048]; }
        return;
    }
    __shared__ float tile[32][33];
    const float* W; __half* out; int K, N, ti;
    if (bid < 1762)      { W = l1fWi; out = l1Wi16;                       K = 256;  N = 2048; ti = bid - 1250; }
    else if (bid < 2274) { W = l1bWi; out = l1Wi16 + (size_t)2048 * 256;  K = 256;  N = 2048; ti = bid - 1762; }
    else if (bid < 4322) { W = l2fWi; out = l2Wi16;                       K = 1024; N = 2048; ti = bid - 2274; }
    else if (bid < 6370) { W = l2bWi; out = l2Wi16 + (size_t)2048 * 1024; K = 1024; N = 2048; ti = bid - 4322; }
    else if (bid < 9442) { W = W1;    out = W1T;                          K = 3072; N = 1024; ti = bid - 6370; }
    else                 { W = W2;    out = W2T;                          K = 1024; N = 512;  ti = bid - 9442; }
    int ntx = N >> 5;
    int n0 = (ti % ntx) * 32, k0 = (ti / ntx) * 32;
    int tx = tid & 31, ty = tid >> 5;
    for (int i = ty; i < 32; i += 8)
        tile[i][tx] = W[(size_t)(k0 + i) * N + n0 + tx];
    __syncthreads();
    for (int i = ty; i < 32; i += 8)
        out[(size_t)(n0 + i) * K + k0 + tx] = __float2half(tile[tx][i]);
}

// ================= fp16 GEMM, 256x128 tile, 512 thr (projections) ==========
#define HAS 36
#define GAB (256*HAS)
#define GBB (128*HAS)
#define BIG_SMEM ((2*(GAB+GBB))*4)  // 110592 B

__global__ void __launch_bounds__(512)
h16_gemm_big(const __half* __restrict__ A, const __half* __restrict__ emb,
             const int* __restrict__ seq, int K,
             const __half* __restrict__ WT, const float* __restrict__ bias,
             __half* __restrict__ C, int cstride) {
    extern __shared__ unsigned sm[];
    unsigned* Asw = sm;                 // [2][256][HAS]
    unsigned* Bsw = sm + 2 * GAB;       // [2][128][HAS]

    int n0 = blockIdx.x * 128;
    int m0 = blockIdx.y * 256;
    int tid = threadIdx.x;
    int wid = tid >> 5, lane = tid & 31;
    int g = lane >> 2, tg = lane & 3;
    int wm = (wid >> 2) * 64;
    int wn = (wid & 3) * 32;

    int ar = tid >> 1;
    int aseg = tid & 1;
    const __half* Arow = seq ? (emb + (size_t)seq[m0 + ar] * K)
                             : (A + (size_t)(m0 + ar) * K);
    int br = tid >> 2;
    int bseg = tid & 3;
    const __half* Brow = WT + (size_t)(n0 + br) * K;

    int j8 = lane >> 3, r8 = lane & 7;
    unsigned smA = (unsigned)__cvta_generic_to_shared(Asw);
    unsigned smB = (unsigned)__cvta_generic_to_shared(Bsw);
    unsigned aoffL[4], boffL[2];
#pragma unroll
    for (int mi = 0; mi < 4; mi++)
        aoffL[mi] = ((wm + mi * 16 + (j8 & 1) * 8 + r8) * HAS + (j8 >> 1) * 4) * 4;
#pragma unroll
    for (int np = 0; np < 2; np++)
        boffL[np] = ((wn + np * 16 + (j8 >> 1) * 8 + r8) * HAS + (j8 & 1) * 4) * 4;

    int niter = K >> 6;

#define GSTAGE(IT, BUF) do {                                                   \
        int k0 = (IT) << 6;                                                    \
        unsigned* ad = Asw + (BUF) * GAB + ar * HAS + aseg * 16;               \
        const __half* as = Arow + k0 + aseg * 32;                              \
        cp16(ad, as); cp16(ad + 4, as + 8);                                    \
        cp16(ad + 8, as + 16); cp16(ad + 12, as + 24);                         \
        unsigned* bd = Bsw + (BUF) * GBB + br * HAS + bseg * 8;                \
        const __half* bs = Brow + k0 + bseg * 16;                              \
        cp16(bd, bs); cp16(bd + 4, bs + 8);                                    \
        asm volatile("cp.async.commit_group;\n");                              \
    } while (0)

    float acc[4][4][4] = {};

    GSTAGE(0, 0);
    for (int it = 0; it < niter; it++) {
        int buf = it & 1;
        if (it + 1 < niter) {
            GSTAGE(it + 1, buf ^ 1);
            asm volatile("cp.async.wait_group 1;\n");
        } else {
            asm volatile("cp.async.wait_group 0;\n");
        }
        __syncthreads();
        unsigned abase = smA + buf * GAB * 4;
        unsigned bbase = smB + buf * GBB * 4;
#pragma unroll
        for (int kk = 0; kk < 4; kk++) {
            unsigned koff = kk * 32;
            unsigned a[4][4], b[2][4];
#pragma unroll
            for (int mi = 0; mi < 4; mi++) ldsm_x4(a[mi], abase + aoffL[mi] + koff);
#pragma unroll
            for (int np = 0; np < 2; np++) ldsm_x4(b[np], bbase + boffL[np] + koff);
#pragma unroll
            for (int mi = 0; mi < 4; mi++) {
#pragma unroll
                for (int np = 0; np < 2; np++) {
                    mma_f16(acc[mi][np * 2],     a[mi], b[np]);
                    mma_f16(acc[mi][np * 2 + 1], a[mi], b[np] + 2);
                }
            }
        }
        __syncthreads();
    }
#undef GSTAGE

#pragma unroll
    for (int mi = 0; mi < 4; mi++) {
#pragma unroll
        for (int rh = 0; rh < 2; rh++) {
            int row = m0 + wm + mi * 16 + g + rh * 8;
#pragma unroll
            for (int ni = 0; ni < 4; ni++) {
                int cl = wn + ni * 8 + 2 * tg;
                float v0 = acc[mi][ni][rh * 2 + 0] + bias[n0 + cl];
                float v1 = acc[mi][ni][rh * 2 + 1] + bias[n0 + cl + 1];
                __half2 hv = __floats2half2_rn(v0, v1);
                *(__half2*)(C + (size_t)row * cstride + n0 + cl) = hv;
            }
        }
    }
}

// ================= fp16 split-K GEMM (MLP), 128x128, fp32 partials =========
// If pooled16 != null, A is the virtual feats matrix [256,3072].
#define HBUF (128*HAS)
#define H16_SMEM (4*HBUF*4)

__global__ void __launch_bounds__(256)
h16_splitk(const __half* __restrict__ A, int lda,
           const __half* __restrict__ pooled16, const __half* __restrict__ hfin,
           const __half* __restrict__ WT, int ldw, int Ksp,
           float* __restrict__ part, int N, int MN) {
    extern __shared__ unsigned sm[];
    unsigned* Asw = sm;
    unsigned* Bsw = sm + 2 * HBUF;

    int n0 = blockIdx.x * 128;
    int m0 = blockIdx.y * 128;
    int koffb = blockIdx.z * Ksp;
    int tid = threadIdx.x;
    int wid = tid >> 5, lane = tid & 31;
    int g = lane >> 2, tg = lane & 3;
    int wm = (wid >> 2) * 64;
    int wn = (wid & 3) * 32;

    int ar = tid >> 1;
    int aseg = tid & 1;
    const __half* Brow = WT + (size_t)(n0 + ar) * ldw + koffb;

    int j8 = lane >> 3, r8 = lane & 7;
    unsigned smA = (unsigned)__cvta_generic_to_shared(Asw);
    unsigned smB = (unsigned)__cvta_generic_to_shared(Bsw);
    unsigned aoffL[4], boffL[2];
#pragma unroll
    for (int mi = 0; mi < 4; mi++)
        aoffL[mi] = ((wm + mi * 16 + (j8 & 1) * 8 + r8) * HAS + (j8 >> 1) * 4) * 4;
#pragma unroll
    for (int np = 0; np < 2; np++)
        boffL[np] = ((wn + np * 16 + (j8 >> 1) * 8 + r8) * HAS + (j8 & 1) * 4) * 4;

    int niter = Ksp >> 6;

#define SSTAGE(IT, BUF) do {                                                   \
        int k0 = (IT) << 6;                                                    \
        int cbase = koffb + k0 + aseg * 32;                                    \
        const __half* as = pooled16                                             \
            ? feats_ptr(pooled16, hfin, m0 + ar, cbase)                         \
            : (A + (size_t)(m0 + ar) * lda + cbase);                            \
        unsigned* ad = Asw + (BUF) * HBUF + ar * HAS + aseg * 16;              \
        cp16(ad, as); cp16(ad + 4, as + 8);                                    \
        cp16(ad + 8, as + 16); cp16(ad + 12, as + 24);                         \
        unsigned* bd = Bsw + (BUF) * HBUF + ar * HAS + aseg * 16;              \
        const __half* bs = Brow + k0 + aseg * 32;                              \
        cp16(bd, bs); cp16(bd + 4, bs + 8);                                    \
        cp16(bd + 8, bs + 16); cp16(bd + 12, bs + 24);                         \
        asm volatile("cp.async.commit_group;\n");                              \
    } while (0)

    float acc[4][4][4] = {};

    SSTAGE(0, 0);
    for (int it = 0; it < niter; it++) {
        int buf = it & 1;
        if (it + 1 < niter) {
            SSTAGE(it + 1, buf ^ 1);
            asm volatile("cp.async.wait_group 1;\n");
        } else {
            asm volatile("cp.async.wait_group 0;\n");
        }
        __syncthreads();
        unsigned abase = smA + buf * HBUF * 4;
        unsigned bbase = smB + buf * HBUF * 4;
#pragma unroll
        for (int kk = 0; kk < 4; kk++) {
            unsigned koff = kk * 32;
            unsigned a[4][4], b[2][4];
#pragma unroll
            for (int mi = 0; mi < 4; mi++) ldsm_x4(a[mi], abase + aoffL[mi] + koff);
#pragma unroll
            for (int np = 0; np < 2; np++) ldsm_x4(b[np], bbase + boffL[np] + koff);
#pragma unroll
            for (int mi = 0; mi < 4; mi++) {
#pragma unroll
                for (int np = 0; np < 2; np++) {
                    mma_f16(acc[mi][np * 2],     a[mi], b[np]);
                    mma_f16(acc[mi][np * 2 + 1], a[mi], b[np] + 2);
                }
            }
        }
        __syncthreads();
    }
#undef SSTAGE

    float* pbase = part + (size_t)blockIdx.z * MN;
#pragma unroll
    for (int mi = 0; mi < 4; mi++) {
#pragma unroll
        for (int rh = 0; rh < 2; rh++) {
            int row = m0 + wm + mi * 16 + g + rh * 8;
#pragma unroll
            for (int ni = 0; ni < 4; ni++) {
                int cl = wn + ni * 8 + 2 * tg;
                *(float2*)(pbase + (size_t)row * N + n0 + cl) =
                    make_float2(acc[mi][ni][rh * 2 + 0], acc[mi][ni][rh * 2 + 1]);
            }
        }
    }
}

__global__ void splitk_reduce(const float* __restrict__ part, const float* __restrict__ bias,
                              __half* __restrict__ out, int MN, int Nmask, int SK) {
    int i = blockIdx.x * 256 + threadIdx.x;
    if (i >= MN) return;
    float s = bias[i & Nmask];
    for (int k = 0; k < SK; k++) s += part[(size_t)k * MN + i];
    s = fmaxf(s, 0.f);
    out[i] = __float2half(s);
}

// ================= persistent BiLSTM recurrence (R11 exact) ================
#define BS2 260
#define MS2 260
#define XS 36
#define ZS_STRIDE 68
#define REC_SMEM ((64*BS2 + 128*MS2 + 128*XS) * 4)   // 218112 B

__global__ void __launch_bounds__(256, 1)
rec_persistent(__half* __restrict__ hbuf0, __half* __restrict__ hbuf1,
               const float* __restrict__ WhF, const float* __restrict__ WhB,
               const __half* __restrict__ xw, const int* __restrict__ seq,
               __half* __restrict__ out_seq) {
    extern __shared__ unsigned smem_dyn[];
    unsigned* Bsw = smem_dyn;
    unsigned* Asw = smem_dyn + 64 * BS2;
    unsigned* Xsw = smem_dyn + 64 * BS2 + 128 * MS2;
    float* zs = (float*)Asw;

    int tid = threadIdx.x;
    int bn = blockIdx.x & 63;
    int bm = blockIdx.x >> 6;
    int dir = bn >> 5;
    int ub = (bn & 31) * 16;
    int m0 = bm * 128;
    int gid = bm * 2 + dir;
    const float* W = dir ? WhB : WhF;

    int wid = tid >> 5, lane = tid & 31;
    int g = lane >> 2, tg = lane & 3;
    int wm = (wid >> 1) * 32;
    int wn = (wid & 1) * 32;

    for (int jj = tid; jj < 64 * 256; jj += 256) {
        int k2 = jj >> 6, cl = jj & 63;
        int nc = (cl >> 4) * 512 + ub + (cl & 15);
        float lo = W[(size_t)(2 * k2) * G4 + nc];
        float hi = W[(size_t)(2 * k2 + 1) * G4 + nc];
        __half2 hv = __floats2half2_rn(lo, hi);
        Bsw[cl * BS2 + k2] = *(unsigned*)&hv;
    }

    int j8 = lane >> 3, r8 = lane & 7;
    unsigned smA = (unsigned)__cvta_generic_to_shared(Asw);
    unsigned smB = (unsigned)__cvta_generic_to_shared(Bsw);
    unsigned aoff[2], boff[2];
#pragma unroll
    for (int mi = 0; mi < 2; mi++)
        aoff[mi] = smA + ((wm + mi * 16 + (j8 & 1) * 8 + r8) * MS2 + (j8 >> 1) * 4) * 4;
#pragma unroll
    for (int np = 0; np < 2; np++)
        boff[np] = smB + ((wn + np * 16 + (j8 >> 1) * 8 + r8) * BS2 + (j8 & 1) * 4) * 4;

    float creg[8], hreg[8];
#pragma unroll
    for (int e = 0; e < 8; e++) { creg[e] = 0.f; hreg[e] = 0.f; }

    int ar = tid >> 1;
    int ah0 = (tid & 1) * 256;
    int xrow = tid >> 1;
    int xseg2 = (tid & 1) * 2;
    int grow = tid >> 1;
    int guu0 = (tid & 1) * 8;
    __syncthreads();

    {
        int te0 = dir ? (Tlen - 1) : 0;
        const __half* xrowp = xw + ((size_t)(m0 + xrow) * Tlen + te0) * N2 + dir * G4 + ub;
        unsigned* xd = Xsw + xrow * XS + xseg2 * 8;
#pragma unroll
        for (int s = 0; s < 2; s++) {
            const __half* src = xrowp + (xseg2 + s) * 512;
            cp16(xd + s * 8, src);
            cp16(xd + s * 8 + 4, src + 8);
        }
        asm volatile("cp.async.commit_group;\n");
    }

    for (int t = 0; t < Tlen; t++) {
        int te = dir ? (Tlen - 1 - t) : t;
        const __half* hcur = (t & 1) ? hbuf1 : hbuf0;
        __half* hnxt = (t & 1) ? hbuf0 : hbuf1;

        if (t > 0) {
            const __half* srch = hcur + dir * (Bsz * UNITS) + (size_t)(m0 + ar) * UNITS + ah0;
            unsigned* dstw = Asw + ar * MS2 + (ah0 >> 1);
#pragma unroll
            for (int i = 0; i < 32; i++) cp16(dstw + i * 4, srch + i * 8);
            asm volatile("cp.async.commit_group;\n");
        }
        asm volatile("cp.async.wait_group 0;\n");
        __syncthreads();

        float acc[2][4][4] = {};
        if (t > 0) {
#pragma unroll 4
            for (int kk = 0; kk < 32; kk++) {
                unsigned koff = kk * 32;
                unsigned a[2][4], b[2][4];
                ldsm_x4(a[0], aoff[0] + koff);
                ldsm_x4(a[1], aoff[1] + koff);
                ldsm_x4(b[0], boff[0] + koff);
                ldsm_x4(b[1], boff[1] + koff);
#pragma unroll
                for (int mi = 0; mi < 2; mi++) {
#pragma unroll
                    for (int np = 0; np < 2; np++) {
                        mma_f16(acc[mi][np * 2],     a[mi], b[np]);
                        mma_f16(acc[mi][np * 2 + 1], a[mi], b[np] + 2);
                    }
                }
            }
        }
        __syncthreads();

#pragma unroll
        for (int mi = 0; mi < 2; mi++) {
#pragma unroll
            for (int rh = 0; rh < 2; rh++) {
                int lrow = wm + mi * 16 + g + rh * 8;
#pragma unroll
                for (int ni = 0; ni < 4; ni++) {
                    int cl = wn + ni * 8 + 2 * tg;
                    int gate = cl >> 4, uu = cl & 15;
                    unsigned xu = Xsw[lrow * XS + gate * 8 + (uu >> 1)];
                    float2 xv = __half22float2(*(__half2*)&xu);
                    zs[lrow * ZS_STRIDE + cl]     = acc[mi][ni][rh * 2 + 0] + xv.x;
                    zs[lrow * ZS_STRIDE + cl + 1] = acc[mi][ni][rh * 2 + 1] + xv.y;
                }
            }
        }
        __syncthreads();

        if (t + 1 < Tlen) {
            int ten = dir ? (Tlen - 2 - t) : (t + 1);
            const __half* xrowp = xw + ((size_t)(m0 + xrow) * Tlen + ten) * N2 + dir * G4 + ub;
            unsigned* xd = Xsw + xrow * XS + xseg2 * 8;
#pragma unroll
            for (int s = 0; s < 2; s++) {
                const __half* src = xrowp + (xseg2 + s) * 512;
                cp16(xd + s * 8, src);
                cp16(xd + s * 8 + 4, src + 8);
            }
            asm volatile("cp.async.commit_group;\n");
        }

        {
            int b = m0 + grow;
            bool live = (seq[b * Tlen + te] != 0);
            const float* zb = zs + grow * ZS_STRIDE + guu0;
            float zi[8], zf[8], zg[8], zo[8];
            *(float4*)&zi[0] = *(const float4*)(zb);      *(float4*)&zi[4] = *(const float4*)(zb + 4);
            *(float4*)&zf[0] = *(const float4*)(zb + 16); *(float4*)&zf[4] = *(const float4*)(zb + 20);
            *(float4*)&zg[0] = *(const float4*)(zb + 32); *(float4*)&zg[4] = *(const float4*)(zb + 36);
            *(float4*)&zo[0] = *(const float4*)(zb + 48); *(float4*)&zo[4] = *(const float4*)(zb + 52);
#pragma unroll
            for (int e = 0; e < 8; e++) {
                float si = sig_fast(zi[e]);
                float sf = sig_fast(zf[e]);
                float so = sig_fast(zo[e]);
                float cn = sf * creg[e] + si * tanh_fast(zg[e]);
                float hn = so * tanh_fast(cn);
                if (live) { creg[e] = cn; hreg[e] = hn; }
            }
            __half2 p[4];
#pragma unroll
            for (int q = 0; q < 4; q++) p[q] = __floats2half2_rn(hreg[2 * q], hreg[2 * q + 1]);
            uint4 pk = *(uint4*)p;
            *(uint4*)(hnxt + dir * (Bsz * UNITS) + b * UNITS + ub + guu0) = pk;
            if (out_seq)
                *(uint4*)(out_seq + ((size_t)b * Tlen + te) * 1024 + dir * 512 + ub + guu0) = pk;
        }
        group_barrier(gid);
    }
}

// ---------------- final: sigmoid(x2 @ W3 + b3) -----------------------------
__global__ void final_kernel(const __half* __restrict__ x2, const float* __restrict__ W3,
                             const float* __restrict__ b3, float* __restrict__ out) {
    int b = blockIdx.x;
    float s = 0.f;
    for (int k = threadIdx.x; k < 512; k += 128)
        s += __half2float(x2[b * 512 + k]) * W3[k];
    for (int o = 16; o > 0; o >>= 1) s += __shfl_down_sync(0xffffffffu, s, o);
    __shared__ float red[4];
    if ((threadIdx.x & 31) == 0) red[threadIdx.x >> 5] = s;
    __syncthreads();
    if (threadIdx.x == 0) {
        float t = red[0] + red[1] + red[2] + red[3] + b3[0];
        out[b] = 1.f / (1.f + expf(-t));
    }
}

// ---------------------------------------------------------------------------
extern "C" void kernel_launch(void* const* d_in, const int* in_sizes, int n_in,
                              void* d_out, int out_size) {
    const float* enc    = (const float*)d_in[0];
    const int*   seq    = (const int*)d_in[1];
    const float* emb    = (const float*)d_in[2];
    const float* l1f_Wi = (const float*)d_in[3];
    const float* l1f_Wh = (const float*)d_in[4];
    const float* l1f_b  = (const float*)d_in[5];
    const float* l1b_Wi = (const float*)d_in[6];
    const float* l1b_Wh = (const float*)d_in[7];
    const float* l1b_b  = (const float*)d_in[8];
    const float* l2f_Wi = (const float*)d_in[9];
    const float* l2f_Wh = (const float*)d_in[10];
    const float* l2f_b  = (const float*)d_in[11];
    const float* l2b_Wi = (const float*)d_in[12];
    const float* l2b_Wh = (const float*)d_in[13];
    const float* l2b_b  = (const float*)d_in[14];
    const float* W1     = (const float*)d_in[15];
    const float* b1     = (const float*)d_in[16];
    const float* W2     = (const float*)d_in[17];
    const float* b2     = (const float*)d_in[18];
    const float* W3     = (const float*)d_in[19];
    const float* b3     = (const float*)d_in[20];
    float* out = (float*)d_out;

    float *bias1, *bias2, *part;
    __half *pooled16, *xw16, *seq1h, *hh0, *hh1, *emb16, *l1Wi16, *l2Wi16, *W1T, *W2T, *x1h, *x2h;
    cudaGetSymbolAddress((void**)&pooled16, g_pooled16);
    cudaGetSymbolAddress((void**)&xw16, g_xw16);
    cudaGetSymbolAddress((void**)&seq1h, g_seq1h);
    cudaGetSymbolAddress((void**)&hh0, g_hh0);
    cudaGetSymbolAddress((void**)&hh1, g_hh1);
    cudaGetSymbolAddress((void**)&emb16, g_emb16);
    cudaGetSymbolAddress((void**)&l1Wi16, g_l1Wi16);
    cudaGetSymbolAddress((void**)&l2Wi16, g_l2Wi16);
    cudaGetSymbolAddress((void**)&W1T, g_W1T);
    cudaGetSymbolAddress((void**)&W2T, g_W2T);
    cudaGetSymbolAddress((void**)&bias1, g_bias1);
    cudaGetSymbolAddress((void**)&bias2, g_bias2);
    cudaGetSymbolAddress((void**)&x1h, g_x1h);
    cudaGetSymbolAddress((void**)&x2h, g_x2h);
    cudaGetSymbolAddress((void**)&part, g_part);

    cudaFuncSetAttribute(rec_persistent,
                         cudaFuncAttributeMaxDynamicSharedMemorySize, REC_SMEM);
    cudaFuncSetAttribute(h16_gemm_big,
                         cudaFuncAttributeMaxDynamicSharedMemorySize, BIG_SMEM);
    cudaFuncSetAttribute(h16_splitk,
                         cudaFuncAttributeMaxDynamicSharedMemorySize, H16_SMEM);

    __half* hfinal = hh0;   // t=63 (odd) writes hbuf0

    // 0: fused prologue (conversions + pooled mean -> fp16)
    prep_kernel<<<PREP_BLOCKS, 256>>>(emb, l1f_Wi, l1b_Wi, l2f_Wi, l2b_Wi, W1, W2,
                                      l1f_b, l1b_b, l2f_b, l2b_b, enc,
                                      emb16, l1Wi16, l2Wi16, W1T, W2T,
                                      bias1, bias2, pooled16);
    // 1: layer-1 input projection (256x128 big tile, fused gather)
    h16_gemm_big<<<dim3(N2 / 128, ROWS / 256), 512, BIG_SMEM>>>(
        nullptr, emb16, seq, EMB, l1Wi16, bias1, xw16, N2);
    // 2: layer-1 recurrence (R11 config)
    rec_persistent<<<128, 256, REC_SMEM>>>(hh0, hh1, l1f_Wh, l1b_Wh, xw16, seq, seq1h);
    // 3: layer-2 input projection (256x128 big tile)
    h16_gemm_big<<<dim3(N2 / 128, ROWS / 256), 512, BIG_SMEM>>>(
        seq1h, nullptr, nullptr, 1024, l2Wi16, bias2, xw16, N2);
    // 4: layer-2 recurrence
    rec_persistent<<<128, 256, REC_SMEM>>>(hh0, hh1, l2f_Wh, l2b_Wh, xw16, seq, nullptr);
    // 5-6: MLP layer 1 (split-K 4, concat fused into A-loader)
    h16_splitk<<<dim3(1024 / 128, Bsz / 128, 4), 256, H16_SMEM>>>(
        nullptr, 0, pooled16, hfinal, W1T, 3072, 768, part, 1024, Bsz * 1024);
    splitk_reduce<<<(Bsz * 1024 + 255) / 256, 256>>>(part, b1, x1h, Bsz * 1024, 1023, 4);
    // 7-8: MLP layer 2 (split-K 4)
    h16_splitk<<<dim3(512 / 128, Bsz / 128, 4), 256, H16_SMEM>>>(
        x1h, 1024, nullptr, nullptr, W2T, 1024, 256, part, 512, Bsz * 512);
    splitk_reduce<<<(Bsz * 512 + 255) / 256, 256>>>(part, b2, x2h, Bsz * 512, 511, 4);
    // 9: final sigmoid
    final_kernel<<<Bsz, 128>>>(x2h, W3, b3, out);
}